// round 7
// baseline (speedup 1.0000x reference)
#include <cuda_runtime.h>
#include <cuda_bf16.h>
#include <math.h>

// Problem constants
#define B_   16
#define L_   256
#define LQ_  64
#define ET_  128
#define H_   4
#define ETK_ 32
#define DIM_ 64
#define D_IN_ 32
#define IE_  8

typedef unsigned long long ull;

// ---------------- scratch (device globals; no allocation) ----------------
__device__ float g_q[H_ * LQ_ * ETK_];          // (h, q, e)  pre-scaled by 1/sqrt(32)
__device__ float g_k[B_ * H_ * L_ * ETK_];      // (b, h, l, e)
__device__ float g_att[B_ * LQ_ * ET_];         // (b, q, h*32+d)  compact (ones folded)
__device__ float g_Wc[ET_ * ET_];               // 128 x 128 : compact rows of Wo @ W_ih
__device__ float g_bc[ET_];                     // combined bias (incl. ones-rows fold)
__device__ float g_pre[B_ * LQ_ * ET_];         // (b, t, j)

// ======================================================================
// Kernel 1 (fused): time-embed + Q/K projections  AND  Wc/bc combine.
// ======================================================================
__global__ void stage1_kernel(
    const float* __restrict__ times, const float* __restrict__ query,
    const float* __restrict__ w_lin, const float* __restrict__ b_lin,
    const float* __restrict__ w_per, const float* __restrict__ b_per,
    const float* __restrict__ Wk, const float* __restrict__ bk,
    const float* __restrict__ Wq, const float* __restrict__ bq,
    const float* __restrict__ Wo, const float* __restrict__ bo,
    const float* __restrict__ W_ih, const float* __restrict__ b_ih,
    const float* __restrict__ b_hh)
{
    extern __shared__ float sm[];
    float* s_a = sm;              // 16 x 128
    float* s_w = sm + 16 * 128;   // 128 x 128
    __shared__ float tv[16];

    const int tid = threadIdx.x;
    const int bx  = blockIdx.x;
    const int tx = tid & 31;
    const int ty = tid >> 5;

    if (bx < 260) {
        const bool is_q = (bx >= 256);
        const int r0 = bx * 16;
        if (tid < 16) tv[tid] = is_q ? query[r0 - 4096 + tid] : times[r0 + tid];
        __syncthreads();

        const float wl = w_lin[0], bl = b_lin[0];
        for (int idx = tid; idx < 16 * 128; idx += 256) {
            int r = idx >> 7, c = idx & 127;
            float t = tv[r];
            s_a[idx] = (c == 0) ? fmaf(t, wl, bl)
                                : __sinf(fmaf(t, w_per[c - 1], b_per[c - 1]));
        }
        const float* W    = is_q ? Wq : Wk;
        const float* bias = is_q ? bq : bk;
#pragma unroll
        for (int idx = tid * 4; idx < 128 * 128; idx += 1024)
            *(float4*)(s_w + idx) = *(const float4*)(W + idx);
        __syncthreads();

        float acc[2][4];
#pragma unroll
        for (int r = 0; r < 2; r++)
#pragma unroll
            for (int c = 0; c < 4; c++) acc[r][c] = 0.f;

#pragma unroll 4
        for (int i = 0; i < 128; i++) {
            float4 w = *(const float4*)(s_w + i * 128 + 4 * tx);
            float e0 = s_a[(2 * ty) * 128 + i];
            float e1 = s_a[(2 * ty + 1) * 128 + i];
            acc[0][0] = fmaf(e0, w.x, acc[0][0]); acc[0][1] = fmaf(e0, w.y, acc[0][1]);
            acc[0][2] = fmaf(e0, w.z, acc[0][2]); acc[0][3] = fmaf(e0, w.w, acc[0][3]);
            acc[1][0] = fmaf(e1, w.x, acc[1][0]); acc[1][1] = fmaf(e1, w.y, acc[1][1]);
            acc[1][2] = fmaf(e1, w.z, acc[1][2]); acc[1][3] = fmaf(e1, w.w, acc[1][3]);
        }

        const float scale = is_q ? 0.17677669529663687f : 1.0f;
#pragma unroll
        for (int r = 0; r < 2; r++) {
            int grow = r0 + 2 * ty + r;
#pragma unroll
            for (int c = 0; c < 4; c++) {
                int col = 4 * tx + c;
                float v = (acc[r][c] + bias[col]) * scale;
                int h = col >> 5, e = col & 31;
                if (is_q) g_q[(h * LQ_ + (grow - 4096)) * ETK_ + e] = v;
                else {
                    int b = grow >> 8, l = grow & 255;
                    g_k[((b * H_ + h) * L_ + l) * ETK_ + e] = v;
                }
            }
        }
    } else if (bx < 268) {
        const int cr0 = (bx - 260) * 16;
        for (int idx = tid; idx < 16 * 128; idx += 256) {
            int rr = idx >> 7, c = idx & 127;
            int cr = cr0 + rr;
            int r = (cr >> 5) * 64 + (cr & 31);
            s_a[idx] = Wo[r * 128 + c];
        }
#pragma unroll
        for (int idx = tid * 4; idx < 128 * 128; idx += 1024)
            *(float4*)(s_w + idx) = *(const float4*)(W_ih + idx);
        __syncthreads();

        float acc[2][4];
#pragma unroll
        for (int r = 0; r < 2; r++)
#pragma unroll
            for (int c = 0; c < 4; c++) acc[r][c] = 0.f;

#pragma unroll 4
        for (int i = 0; i < 128; i++) {
            float4 w = *(const float4*)(s_w + i * 128 + 4 * tx);
            float e0 = s_a[(2 * ty) * 128 + i];
            float e1 = s_a[(2 * ty + 1) * 128 + i];
            acc[0][0] = fmaf(e0, w.x, acc[0][0]); acc[0][1] = fmaf(e0, w.y, acc[0][1]);
            acc[0][2] = fmaf(e0, w.z, acc[0][2]); acc[0][3] = fmaf(e0, w.w, acc[0][3]);
            acc[1][0] = fmaf(e1, w.x, acc[1][0]); acc[1][1] = fmaf(e1, w.y, acc[1][1]);
            acc[1][2] = fmaf(e1, w.z, acc[1][2]); acc[1][3] = fmaf(e1, w.w, acc[1][3]);
        }
#pragma unroll
        for (int r = 0; r < 2; r++)
#pragma unroll
            for (int c = 0; c < 4; c++)
                g_Wc[(cr0 + 2 * ty + r) * 128 + 4 * tx + c] = acc[r][c];
    } else {
        const int j = tid & 127, hf = tid >> 7;
        float accv = 0.f;
#pragma unroll 4
        for (int i = 0; i < 64; i++) {
            int oi = hf * 64 + i;
            int r = (oi >> 5) * 64 + 32 + (oi & 31);
            accv += Wo[r * 128 + j];
        }
        s_a[hf * 128 + j] = accv;
        __syncthreads();
        float v = 0.f;
        if (tid < 128) v = bo[tid] + s_a[tid] + s_a[128 + tid];
        __syncthreads();
        if (tid < 128) s_a[tid] = v;
#pragma unroll
        for (int idx = tid * 4; idx < 128 * 128; idx += 1024)
            *(float4*)(s_w + idx) = *(const float4*)(W_ih + idx);
        __syncthreads();
        if (tid < 128) {
            float acc = b_ih[tid] + b_hh[tid];
#pragma unroll 8
            for (int i = 0; i < 128; i++)
                acc = fmaf(s_a[i], s_w[i * 128 + tid], acc);
            g_bc[tid] = acc;
        }
    }
}

// ======================================================================
// Kernel 2: masked per-feature attention (compact output).
// ======================================================================
__global__ void attn_kernel(const float* __restrict__ x,
                            const float* __restrict__ mask)
{
    extern __shared__ float smem[];
    float*  qv  = smem;
    float*  s_s = smem + 512;
    float2* mxm = (float2*)(smem + 512 + 4096);

    const int tid = threadIdx.x;
    const int qt = blockIdx.x, h = blockIdx.y, b = blockIdx.z;

    qv[tid] = g_q[(h * LQ_ + qt * 16) * ETK_ + tid];

    const float* xb = x    + b * L_ * D_IN_;
    const float* mb = mask + b * L_ * D_IN_;
    for (int idx = tid; idx < L_ * D_IN_; idx += 512) {
        float m = mb[idx];
        mxm[idx] = make_float2(m * xb[idx], m);
    }
    __syncthreads();

    {
        const int k  = tid & 255;
        const int qh = tid >> 8;
        const float* kp = g_k + ((b * H_ + h) * L_ + k) * ETK_;
        float kv[32];
#pragma unroll
        for (int i = 0; i < 8; i++) {
            float4 v = *(const float4*)(kp + 4 * i);
            kv[4 * i] = v.x; kv[4 * i + 1] = v.y; kv[4 * i + 2] = v.z; kv[4 * i + 3] = v.w;
        }
#pragma unroll
        for (int qq = 0; qq < 8; qq++) {
            int q = qh * 8 + qq;
            float acc = 0.f;
#pragma unroll
            for (int e = 0; e < 32; e++) acc = fmaf(qv[q * 32 + e], kv[e], acc);
            s_s[q * 256 + k] = acc;
        }
    }
    __syncthreads();

    {
        const int wq = tid >> 5, lane = tid & 31;
        float vals[8], m = -1e30f;
#pragma unroll
        for (int i = 0; i < 8; i++) {
            vals[i] = s_s[wq * 256 + lane + 32 * i];
            m = fmaxf(m, vals[i]);
        }
#pragma unroll
        for (int off = 16; off; off >>= 1)
            m = fmaxf(m, __shfl_xor_sync(0xffffffffu, m, off));
#pragma unroll
        for (int i = 0; i < 8; i++)
            s_s[wq * 256 + lane + 32 * i] = __expf(vals[i] - m);
    }
    __syncthreads();

    {
        const int q = tid >> 5, d = tid & 31;
        float num = 0.f, den = 0.f;
        const float* ep = s_s + q * 256;
        const float2* vp = mxm + d;
#pragma unroll 4
        for (int k = 0; k < 256; k++) {
            float  e = ep[k];
            float2 v = vp[k * 32];
            num = fmaf(e, v.x, num);
            den = fmaf(e, v.y, den);
        }
        float att = (den > 0.f) ? (num / den) : 0.f;
        g_att[(b * LQ_ + qt * 16 + q) * ET_ + h * ETK_ + d] = att;
    }
}

// ======================================================================
// Kernel 3: pre = att_c @ Wc + bc   (1024 x 128, K=128)
// ======================================================================
__global__ void pre_kernel()
{
    __shared__ float a_s[16 * 128];
    __shared__ float w_s[128 * 32];

    const int tid = threadIdx.x;
    const int cc = blockIdx.x;
    const int r0 = blockIdx.y * 16;

#pragma unroll
    for (int idx = tid * 4; idx < 16 * 128; idx += 1024)
        *(float4*)(a_s + idx) = *(const float4*)(g_att + r0 * 128 + idx);

#pragma unroll
    for (int f = tid * 4; f < 128 * 32; f += 1024) {
        int i = f >> 5, c = f & 31;
        *(float4*)(w_s + f) = *(const float4*)(g_Wc + i * 128 + cc * 32 + c);
    }
    __syncthreads();

    const int tx = tid & 31;
    const int ty = tid >> 5;

    float a0 = 0.f, a1 = 0.f;
#pragma unroll 8
    for (int i = 0; i < 128; i++) {
        float w = w_s[i * 32 + tx];
        a0 = fmaf(a_s[(2 * ty) * 128 + i],     w, a0);
        a1 = fmaf(a_s[(2 * ty + 1) * 128 + i], w, a1);
    }

    const int col = cc * 32 + tx;
    const float bias = g_bc[col];
    g_pre[(r0 + 2 * ty) * 128 + col]     = a0 + bias;
    g_pre[(r0 + 2 * ty + 1) * 128 + col] = a1 + bias;
}

// ======================================================================
// Kernel 4: RNN + regressor. grid 16 x 256 threads (8 warps, 2/SMSP).
// Lane pair (2m, 2m+1) of warp w owns column j = w*16+m; each lane does
// one 64-row half of the dot (32 f32x2 regs), combined via shfl_xor(1).
// pre fully staged in smem; LDS.128 h loads; 1 barrier/step.
// ======================================================================
__device__ __forceinline__ float fast_tanh(float z)
{
    float e2 = __expf(2.f * z);
    return 1.f - __fdividef(2.f, e2 + 1.f);
}

__device__ __forceinline__ void ffma2(ull& acc, ull a, ull b)
{
    asm("fma.rn.f32x2 %0, %1, %2, %0;" : "+l"(acc) : "l"(a), "l"(b));
}
__device__ __forceinline__ ull fadd2(ull a, ull b)
{
    ull r; asm("add.rn.f32x2 %0, %1, %2;" : "=l"(r) : "l"(a), "l"(b)); return r;
}
__device__ __forceinline__ float2 unpack2(ull a)
{
    float2 v; asm("mov.b64 {%0,%1}, %2;" : "=f"(v.x), "=f"(v.y) : "l"(a)); return v;
}

__global__ void __launch_bounds__(256, 1)
rnn_regr_kernel(const float* __restrict__ W_hh,
                const float* __restrict__ r1_w, const float* __restrict__ r1_b,
                const float* __restrict__ r2_w, const float* __restrict__ r2_b,
                const float* __restrict__ r3_w, const float* __restrict__ r3_b,
                const float* __restrict__ r4_w, const float* __restrict__ r4_b,
                float* __restrict__ out)
{
    __shared__ float pre_s[LQ_ * ET_];   // 32 KB: all steps' pre rows
    __shared__ float h2[2][128];
    __shared__ float v_s[128];
    __shared__ float part2[2][128];

    const int tid  = threadIdx.x;
    const int w    = tid >> 5;
    const int l    = tid & 31;
    const int j    = w * 16 + (l >> 1);  // output column 0..127
    const int half = l & 1;              // 64-row half of the dot
    const int i0   = half * 64;

    // Stage entire pre slab into smem (coalesced float4, 8 per thread)
    {
        const float4* src = (const float4*)(g_pre + blockIdx.x * LQ_ * ET_);
        float4* dst = (float4*)pre_s;
#pragma unroll
        for (int i = 0; i < 8; i++)
            dst[tid + 256 * i] = src[tid + 256 * i];
    }

    // Half-column of W_hh in packed f32x2 registers
    ull wreg[32];
#pragma unroll
    for (int k = 0; k < 32; k++) {
        union { float2 f; ull u; } p;
        p.f.x = W_hh[(i0 + 2 * k) * 128 + j];
        p.f.y = W_hh[(i0 + 2 * k + 1) * 128 + j];
        wreg[k] = p.u;
    }
    __syncthreads();

    // step 0 (h_prev = 0)
    if (tid < 128) h2[0][tid] = fast_tanh(pre_s[tid]);
    __syncthreads();

    int cb = 0;
#pragma unroll 1
    for (int step = 1; step < LQ_; step++) {
        const ulonglong2* hp = (const ulonglong2*)(h2[cb] + i0);
        ull a0 = 0, a1 = 0, a2 = 0, a3 = 0;
#pragma unroll
        for (int k = 0; k < 16; k += 2) {
            ulonglong2 p0 = hp[k];
            ulonglong2 p1 = hp[k + 1];
            ffma2(a0, p0.x, wreg[2 * k]);
            ffma2(a1, p0.y, wreg[2 * k + 1]);
            ffma2(a2, p1.x, wreg[2 * k + 2]);
            ffma2(a3, p1.y, wreg[2 * k + 3]);
        }
        ull s01 = fadd2(fadd2(a0, a1), fadd2(a2, a3));
        float2 sv = unpack2(s01);
        float s = sv.x + sv.y;
        s += __shfl_xor_sync(0xffffffffu, s, 1);

        float hn = fast_tanh(pre_s[step * 128 + j] + s);
        if (half == 0) h2[cb ^ 1][j] = hn;
        cb ^= 1;
        __syncthreads();
    }

    // ---------------- regressor: 3 x (128->128), split-K by 2 ----------------
    {
        const float* hin = h2[cb] + i0;
        const float* wp = r1_w + i0 * 128 + j;
        float a0 = 0.f, a1 = 0.f;
#pragma unroll
        for (int i = 0; i < 64; i += 2) {
            a0 = fmaf(hin[i],     wp[i * 128],       a0);
            a1 = fmaf(hin[i + 1], wp[(i + 1) * 128], a1);
        }
        part2[half][j] = a0 + a1;
        __syncthreads();
        if (tid < 128) v_s[tid] = r1_b[tid] + part2[0][tid] + part2[1][tid];
        __syncthreads();
    }
    {
        const float* hin = v_s + i0;
        const float* wp = r2_w + i0 * 128 + j;
        float a0 = 0.f, a1 = 0.f;
#pragma unroll
        for (int i = 0; i < 64; i += 2) {
            a0 = fmaf(hin[i],     wp[i * 128],       a0);
            a1 = fmaf(hin[i + 1], wp[(i + 1) * 128], a1);
        }
        part2[half][j] = a0 + a1;
        __syncthreads();
        if (tid < 128) h2[0][tid] = r2_b[tid] + part2[0][tid] + part2[1][tid];
        __syncthreads();
    }
    {
        const float* hin = h2[0] + i0;
        const float* wp = r3_w + i0 * 128 + j;
        float a0 = 0.f, a1 = 0.f;
#pragma unroll
        for (int i = 0; i < 64; i += 2) {
            a0 = fmaf(hin[i],     wp[i * 128],       a0);
            a1 = fmaf(hin[i + 1], wp[(i + 1) * 128], a1);
        }
        part2[half][j] = a0 + a1;
        __syncthreads();
        if (tid < 128) v_s[tid] = r3_b[tid] + part2[0][tid] + part2[1][tid];
        __syncthreads();
    }

    // final 128 -> 8 (first 4 warps)
    if (tid < 128) {
        const int ww = tid >> 5, lane = tid & 31;
        float vo = v_s[tid];
        float p[8];
#pragma unroll
        for (int o = 0; o < 8; o++)
            p[o] = vo * r4_w[tid * 8 + o];
#pragma unroll
        for (int off = 16; off; off >>= 1)
#pragma unroll
            for (int o = 0; o < 8; o++)
                p[o] += __shfl_xor_sync(0xffffffffu, p[o], off);
        if (lane < 8) part2[0][ww * 8 + lane] = p[lane];
    }
    __syncthreads();
    if (tid < 8)
        out[blockIdx.x * 8 + tid] = part2[0][tid] + part2[0][8 + tid] +
                                    part2[0][16 + tid] + part2[0][24 + tid] + r4_b[tid];
}

// ======================================================================
extern "C" void kernel_launch(void* const* d_in, const int* in_sizes, int n_in,
                              void* d_out, int out_size)
{
    const float* x     = (const float*)d_in[0];
    const float* times = (const float*)d_in[1];
    const float* mask  = (const float*)d_in[2];
    const float* query = (const float*)d_in[3];
    const float* w_lin = (const float*)d_in[4];
    const float* b_lin = (const float*)d_in[5];
    const float* w_per = (const float*)d_in[6];
    const float* b_per = (const float*)d_in[7];
    const float* Wq    = (const float*)d_in[8];
    const float* bq    = (const float*)d_in[9];
    const float* Wk    = (const float*)d_in[10];
    const float* bk    = (const float*)d_in[11];
    const float* Wo    = (const float*)d_in[12];
    const float* bo    = (const float*)d_in[13];
    const float* W_ih  = (const float*)d_in[14];
    const float* b_ih  = (const float*)d_in[15];
    const float* W_hh  = (const float*)d_in[16];
    const float* b_hh  = (const float*)d_in[17];
    const float* r1_w  = (const float*)d_in[18];
    const float* r1_b  = (const float*)d_in[19];
    const float* r2_w  = (const float*)d_in[20];
    const float* r2_b  = (const float*)d_in[21];
    const float* r3_w  = (const float*)d_in[22];
    const float* r3_b  = (const float*)d_in[23];
    const float* r4_w  = (const float*)d_in[24];
    const float* r4_b  = (const float*)d_in[25];
    float* out = (float*)d_out;

    const int S1_SMEM = (16 * 128 + 128 * 128) * 4;  // 73728
    cudaFuncSetAttribute(stage1_kernel,
                         cudaFuncAttributeMaxDynamicSharedMemorySize, S1_SMEM);
    stage1_kernel<<<269, 256, S1_SMEM>>>(times, query, w_lin, b_lin, w_per, b_per,
                                         Wk, bk, Wq, bq, Wo, bo, W_ih, b_ih, b_hh);

    const int ATTN_SMEM = (512 + 4096) * 4 + 256 * 32 * 8;  // 83968
    cudaFuncSetAttribute(attn_kernel,
                         cudaFuncAttributeMaxDynamicSharedMemorySize, ATTN_SMEM);
    attn_kernel<<<dim3(4, 4, 16), 512, ATTN_SMEM>>>(x, mask);

    pre_kernel<<<dim3(4, 64), 256>>>();

    rnn_regr_kernel<<<16, 256>>>(W_hh, r1_w, r1_b, r2_w, r2_b,
                                 r3_w, r3_b, r4_w, r4_b, out);
}